// round 15
// baseline (speedup 1.0000x reference)
#include <cuda_runtime.h>
#include <cuda_fp16.h>
#include <cstdint>

// SparseChannelLinear: gather(cols)+fp16 -> fp16 mma.sync m16n8k16 GEMM.
// A fragments stream directly global->registers (L2-resident, coalesced,
// double-buffered one k-tile ahead); smem pipeline carries B only.
// Fused epilogue: active cols = acc+bias, inactive cols = bias.

#define ALPHA_S 0.05f

static constexpr int MT   = 8192;
static constexpr int KC   = 2048;
static constexpr int NR   = 2048;
static constexpr int FIN  = 4096;
static constexpr int FOUT = 4096;
static constexpr int NINACT = FOUT - NR;            // 2048

static constexpr int BM = 64, BN = 128, BK = 64;    // BK elements (4 k16-atoms)
static constexpr int STAGES  = 3;
static constexpr int KTILES  = KC / BK;             // 32
static constexpr int THREADS = 128;                 // 4 warps, 2m x 2n of 32x64

static constexpr int K16S = KC / 16;                // 128 k16-atoms total

// dynamic smem: 3 stages of B (16K each)
static constexpr int OFF_TILES   = 0;
static constexpr int B_BYTES     = BN * BK * 2;           // 16384
static constexpr int STAGE_BYTES = B_BYTES;
static constexpr int SMEM_TOTAL  = STAGES * STAGE_BYTES;  // 49152

// scratch:
// g_xc: A fragments. [m_atom(512)][k16(128)][lane(32)] x uint4 (regs a0..a3)
// g_wt4: B fragments pair-packed (alpha-folded). [n_pair(128)][k16(128)][lane(32)]
__device__ uint4 g_xc [(size_t)(MT / 16) * K16S * 32];
__device__ uint4 g_wt4[(size_t)(NR / 16) * K16S * 32];
__device__ int   g_inact[NINACT];   // sorted list of inactive output channels

// ---------------------------------------------------------------------------
__device__ __forceinline__ uint32_t smem_to_u32(const void* p) {
    uint32_t a;
    asm("{ .reg .u64 t; cvta.to.shared.u64 t, %1; cvt.u32.u64 %0, t; }" : "=r"(a) : "l"(p));
    return a;
}
__device__ __forceinline__ uint32_t pack_h2(float lo, float hi) {
    __half2 h = __floats2half2_rn(lo, hi);
    return *reinterpret_cast<uint32_t*>(&h);
}
#define CP_ASYNC16(dst, src) \
    asm volatile("cp.async.cg.shared.global [%0], [%1], 16;" :: "r"(dst), "l"(src))
#define CP_COMMIT() asm volatile("cp.async.commit_group;" ::: "memory")
#define CP_WAIT1()  asm volatile("cp.async.wait_group 1;" ::: "memory")

#define LDS128(r, addr) \
    asm volatile("ld.shared.v4.b32 {%0,%1,%2,%3}, [%4];" \
        : "=r"((r)[0]), "=r"((r)[1]), "=r"((r)[2]), "=r"((r)[3]) : "r"(addr))

__device__ __forceinline__ void mma_f16(float* c, const uint32_t* a, const uint32_t* b) {
    asm volatile(
        "mma.sync.aligned.m16n8k16.row.col.f32.f16.f16.f32 "
        "{%0,%1,%2,%3}, {%4,%5,%6,%7}, {%8,%9}, {%0,%1,%2,%3};"
        : "+f"(c[0]), "+f"(c[1]), "+f"(c[2]), "+f"(c[3])
        : "r"(a[0]), "r"(a[1]), "r"(a[2]), "r"(a[3]), "r"(b[0]), "r"(b[1]));
}

// ---------------------------------------------------------------------------
// Kernel 1: gather active input channels into fp16 A-fragment-packed layout.
__global__ void gather_kernel(const float* __restrict__ x,
                              const int* __restrict__ cols) {
    int t = blockIdx.x * blockDim.x + threadIdx.x;
    int lane   = t & 31;
    int k16    = (t >> 5) & (K16S - 1);
    int m_atom = t >> 12;
    int lr = lane >> 2, lc = lane & 3;
    const int* cb = cols + k16 * 16;
    int c0 = __ldg(cb + 2 * lc);
    int c1 = __ldg(cb + 2 * lc + 1);
    int c2 = __ldg(cb + 2 * lc + 8);
    int c3 = __ldg(cb + 2 * lc + 9);
    const float* r1 = x + (size_t)(m_atom * 16 + lr) * FIN;
    const float* r2 = r1 + (size_t)8 * FIN;
    uint4 o;
    o.x = pack_h2(__ldg(r1 + c0), __ldg(r1 + c1));
    o.y = pack_h2(__ldg(r2 + c0), __ldg(r2 + c1));
    o.z = pack_h2(__ldg(r1 + c2), __ldg(r1 + c3));
    o.w = pack_h2(__ldg(r2 + c2), __ldg(r2 + c3));
    g_xc[t] = o;
}

// Kernel 1b: weights -> alpha-folded fp16, pair-packed B-fragment layout.
__global__ void wconv_kernel(const float* __restrict__ w) {
    int t = blockIdx.x * blockDim.x + threadIdx.x;
    int lane = t & 31;
    int k16  = (t >> 5) & (K16S - 1);
    int np   = t >> 12;
    int lr = lane >> 2, lc2 = 2 * (lane & 3);
    const float* wlo = w + (size_t)(np * 16 + lr) * KC + k16 * 16 + lc2;
    const float* whi = wlo + (size_t)8 * KC;
    uint4 o;
    o.x = pack_h2(__ldg(wlo)     * ALPHA_S, __ldg(wlo + 1) * ALPHA_S);
    o.y = pack_h2(__ldg(wlo + 8) * ALPHA_S, __ldg(wlo + 9) * ALPHA_S);
    o.z = pack_h2(__ldg(whi)     * ALPHA_S, __ldg(whi + 1) * ALPHA_S);
    o.w = pack_h2(__ldg(whi + 8) * ALPHA_S, __ldg(whi + 9) * ALPHA_S);
    g_wt4[t] = o;
}

// Kernel 1c: build sorted inactive-channel list (1 block, deterministic).
__global__ void inactive_kernel(const int* __restrict__ rows) {
    __shared__ char act[FOUT];
    __shared__ int  base[128];
    const int tid = threadIdx.x;
    for (int i = tid; i < FOUT; i += blockDim.x) act[i] = 0;
    __syncthreads();
    for (int i = tid; i < NR; i += blockDim.x) act[__ldg(&rows[i])] = 1;
    __syncthreads();
    if (tid < 128) {
        int c = 0;
        #pragma unroll
        for (int j = 0; j < 32; ++j) c += !act[tid * 32 + j];
        base[tid] = c;
    }
    __syncthreads();
    if (tid == 0) {
        int s = 0;
        for (int i = 0; i < 128; ++i) { int c = base[i]; base[i] = s; s += c; }
    }
    __syncthreads();
    if (tid < 128) {
        int o = base[tid];
        #pragma unroll
        for (int j = 0; j < 32; ++j) {
            int ch = tid * 32 + j;
            if (!act[ch]) g_inact[o++] = ch;
        }
    }
}

// ---------------------------------------------------------------------------
// Kernel 3: fp16 mma.sync GEMM, A direct-from-global (double-buffered),
// B via 3-stage cp.async smem pipeline. 4 warps (2m x 2n), warp tile 32x64.
__global__ __launch_bounds__(THREADS, 2) void gemm_kernel(
    const float* __restrict__ bias,
    const int* __restrict__ rows,
    float* __restrict__ out)
{
    extern __shared__ char smem[];
    __shared__ int   srows[128];
    __shared__ float sbias[128];
    __shared__ int   sicols[128];
    __shared__ float sibias[128];
    const uint32_t sbase = smem_to_u32(smem);
    const int tid = threadIdx.x;
    const int wid = tid >> 5;
    const int lid = tid & 31;
    const int n0 = blockIdx.x * BN;
    const int m0 = blockIdx.y * BM;

    {
        int r = __ldg(&rows[n0 + tid]);
        srows[tid] = r;
        sbias[tid] = __ldg(&bias[r]);
        int ic = g_inact[n0 + tid];          // this x-tile's inactive slice
        sicols[tid] = ic;
        sibias[tid] = __ldg(&bias[ic]);
    }

    // B stage fill: 1024 16B chunks, 8 per thread.
    auto refillB = [&](int kt, int s) {
        const uint32_t stg = sbase + OFF_TILES + s * STAGE_BYTES;
        #pragma unroll
        for (int i = 0; i < 8; ++i) {
            int c = tid + i * THREADS;       // (p*4 + k16l)*32 + lane
            int p = c >> 7, k16l = (c >> 5) & 3, lane = c & 31;
            int np_g  = (n0 >> 4) + p;
            int k16_g = kt * 4 + k16l;
            CP_ASYNC16(stg + c * 16,
                       (const void*)(g_wt4 + ((size_t)np_g * K16S + k16_g) * 32 + lane));
        }
    };

    refillB(0, 0); CP_COMMIT();
    refillB(1, 1); CP_COMMIT();

    const int ma = (wid & 1) * 2;    // warp m-atom base (2 atoms = 32 rows)
    const int nb = (wid >> 1) * 8;   // warp n-atom base (8 atoms = 64 cols)
    const int pb = (wid >> 1) * 4;   // warp n-pair base (4 pairs)

    // A global per-warp fragment pointers (coalesced 512B per warp load)
    const uint4* aBase0 = g_xc + ((size_t)((m0 >> 4) + ma)     * K16S) * 32 + lid;
    const uint4* aBase1 = g_xc + ((size_t)((m0 >> 4) + ma + 1) * K16S) * 32 + lid;

    float acc[2][8][4];
    #pragma unroll
    for (int mt = 0; mt < 2; ++mt)
        #pragma unroll
        for (int nt = 0; nt < 8; ++nt)
            #pragma unroll
            for (int i = 0; i < 4; ++i) acc[mt][nt][i] = 0.f;

    uint4 aA[2][4], aB[2][4];
    // prologue: A fragments for k-tile 0
    #pragma unroll
    for (int k = 0; k < 4; ++k) {
        aA[0][k] = __ldg(aBase0 + k * 32);
        aA[1][k] = __ldg(aBase1 + k * 32);
    }

    // one k-tile: wait B stage, refill B(kt+2), prefetch A(kt+1) into Anext,
    // run 16 MMAs per k16 step from Acur + smem B.
    #define KTILE_BODY(KT, Acur, Anext)                                          \
    do {                                                                         \
        const int s_ = (KT) % STAGES;                                            \
        CP_WAIT1();                                                              \
        __syncthreads();                                                         \
        if ((KT) + 2 < KTILES) refillB((KT) + 2, ((KT) + 2) % STAGES);           \
        CP_COMMIT();                                                             \
        if ((KT) + 1 < KTILES) {                                                 \
            _Pragma("unroll")                                                    \
            for (int k = 0; k < 4; ++k) {                                        \
                Anext[0][k] = __ldg(aBase0 + (((KT) + 1) * 4 + k) * 32);         \
                Anext[1][k] = __ldg(aBase1 + (((KT) + 1) * 4 + k) * 32);         \
            }                                                                    \
        }                                                                        \
        const uint32_t bW_ = sbase + OFF_TILES + s_ * STAGE_BYTES + lid * 16;    \
        _Pragma("unroll")                                                        \
        for (int k16 = 0; k16 < 4; ++k16) {                                      \
            uint32_t b4_[4][4];                                                  \
            _Pragma("unroll")                                                    \
            for (int j = 0; j < 4; ++j)                                          \
                LDS128(b4_[j], bW_ + ((pb + j) * 4 + k16) * 512);                \
            _Pragma("unroll")                                                    \
            for (int mt = 0; mt < 2; ++mt)                                       \
                _Pragma("unroll")                                                \
                for (int nt = 0; nt < 8; ++nt)                                   \
                    mma_f16(acc[mt][nt],                                         \
                            reinterpret_cast<const uint32_t*>(&Acur[mt][k16]),   \
                            &b4_[nt >> 1][(nt & 1) * 2]);                        \
        }                                                                        \
    } while (0)

    for (int kt = 0; kt < KTILES; kt += 2) {
        KTILE_BODY(kt,     aA, aB);
        KTILE_BODY(kt + 1, aB, aA);
    }
    #undef KTILE_BODY

    // epilogue A: scatter acc + bias to active output channels (alpha in W)
    const int lr = lid >> 2;
    const int lc = lid & 3;
    #pragma unroll
    for (int mt = 0; mt < 2; ++mt) {
        int mA = m0 + (ma + mt) * 16 + lr;
        float* rowA = out + (size_t)mA * FOUT;
        float* rowB = rowA + (size_t)8 * FOUT;
        #pragma unroll
        for (int nt = 0; nt < 8; ++nt) {
            int nloc = (nb + nt) * 8 + lc * 2;
            int r0 = srows[nloc], r1 = srows[nloc + 1];
            float b0 = sbias[nloc], b1 = sbias[nloc + 1];
            rowA[r0] = acc[mt][nt][0] + b0;
            rowA[r1] = acc[mt][nt][1] + b1;
            rowB[r0] = acc[mt][nt][2] + b0;
            rowB[r1] = acc[mt][nt][3] + b1;
        }
    }

    // epilogue B: bias to this CTA's slice of inactive channels.
    #pragma unroll
    for (int i = 0; i < 64; ++i) {
        int idx = tid + i * THREADS;         // 0..8191
        int row = idx >> 7, col = idx & 127;
        out[(size_t)(m0 + row) * FOUT + sicols[col]] = sibias[col];
    }
}

// ---------------------------------------------------------------------------
extern "C" void kernel_launch(void* const* d_in, const int* in_sizes, int n_in,
                              void* d_out, int out_size) {
    const float* x    = (const float*)d_in[0];
    const float* w    = (const float*)d_in[1];
    const float* bias = (const float*)d_in[2];
    const int*   rows = (const int*)d_in[3];
    const int*   cols = (const int*)d_in[4];
    float*       out  = (float*)d_out;

    cudaFuncSetAttribute(gemm_kernel, cudaFuncAttributeMaxDynamicSharedMemorySize,
                         SMEM_TOTAL);

    gather_kernel<<<(MT / 16) * K16S * 32 / 256, 256>>>(x, cols);
    wconv_kernel<<<(NR / 16) * K16S * 32 / 256, 256>>>(w);
    inactive_kernel<<<1, 1024>>>(rows);
    gemm_kernel<<<dim3(NR / BN, MT / BM), THREADS, SMEM_TOTAL>>>(bias, rows, out);
}

// round 16
// speedup vs baseline: 1.1327x; 1.1327x over previous
#include <cuda_runtime.h>
#include <cuda_fp16.h>
#include <cstdint>

// SparseChannelLinear: gather(cols)+fp16 -> fp16 mma.sync m16n8k16 GEMM
// (fragment-packed A, pair-packed B, BM=64, 3 CTAs/SM) -> fused epilogue
// writes active results (scatter+bias) AND inactive channels (bias).

#define ALPHA_S 0.05f

static constexpr int MT   = 8192;
static constexpr int KC   = 2048;
static constexpr int NR   = 2048;
static constexpr int FIN  = 4096;
static constexpr int FOUT = 4096;
static constexpr int NINACT = FOUT - NR;            // 2048

static constexpr int BM = 64, BN = 128, BK = 64;    // BK elements (4 k16-atoms)
static constexpr int STAGES  = 3;
static constexpr int KTILES  = KC / BK;             // 32
static constexpr int THREADS = 128;                 // 4 warps, 2m x 2n of 32x64

static constexpr int K16S = KC / 16;                // 128 k16-atoms total

// dynamic smem: rows cache, bias cache, then 3 stages of (A 8K + B 16K)
static constexpr int OFF_ROWS    = 0;      // 128 x int
static constexpr int OFF_BIAS    = 512;    // 128 x float
static constexpr int OFF_TILES   = 1024;
static constexpr int A_BYTES     = BM * BK * 2;           // 8192
static constexpr int B_BYTES     = BN * BK * 2;           // 16384
static constexpr int STAGE_BYTES = A_BYTES + B_BYTES;     // 24576
static constexpr int SMEM_TOTAL  = OFF_TILES + STAGES * STAGE_BYTES;  // 74752

// scratch:
// g_xc: A fragments. [m_atom(512)][k16(128)][lane(32)] x uint4 (regs a0..a3)
// g_wt4: B fragments pair-packed (alpha-folded). [n_pair(128)][k16(128)][lane(32)]
__device__ uint4 g_xc [(size_t)(MT / 16) * K16S * 32];
__device__ uint4 g_wt4[(size_t)(NR / 16) * K16S * 32];
__device__ int   g_inact[NINACT];   // sorted list of inactive output channels

// ---------------------------------------------------------------------------
__device__ __forceinline__ uint32_t smem_to_u32(const void* p) {
    uint32_t a;
    asm("{ .reg .u64 t; cvta.to.shared.u64 t, %1; cvt.u32.u64 %0, t; }" : "=r"(a) : "l"(p));
    return a;
}
__device__ __forceinline__ uint32_t pack_h2(float lo, float hi) {
    __half2 h = __floats2half2_rn(lo, hi);
    return *reinterpret_cast<uint32_t*>(&h);
}
#define CP_ASYNC16(dst, src) \
    asm volatile("cp.async.cg.shared.global [%0], [%1], 16;" :: "r"(dst), "l"(src))
#define CP_COMMIT() asm volatile("cp.async.commit_group;" ::: "memory")
#define CP_WAIT1()  asm volatile("cp.async.wait_group 1;" ::: "memory")

#define LDS128(r, addr) \
    asm volatile("ld.shared.v4.b32 {%0,%1,%2,%3}, [%4];" \
        : "=r"((r)[0]), "=r"((r)[1]), "=r"((r)[2]), "=r"((r)[3]) : "r"(addr))

__device__ __forceinline__ void mma_f16(float* c, const uint32_t* a, const uint32_t* b) {
    asm volatile(
        "mma.sync.aligned.m16n8k16.row.col.f32.f16.f16.f32 "
        "{%0,%1,%2,%3}, {%4,%5,%6,%7}, {%8,%9}, {%0,%1,%2,%3};"
        : "+f"(c[0]), "+f"(c[1]), "+f"(c[2]), "+f"(c[3])
        : "r"(a[0]), "r"(a[1]), "r"(a[2]), "r"(a[3]), "r"(b[0]), "r"(b[1]));
}

// ---------------------------------------------------------------------------
// Kernel 1: gather active input channels into fp16 A-fragment-packed layout.
__global__ void gather_kernel(const float* __restrict__ x,
                              const int* __restrict__ cols) {
    int t = blockIdx.x * blockDim.x + threadIdx.x;
    int lane   = t & 31;
    int k16    = (t >> 5) & (K16S - 1);
    int m_atom = t >> 12;
    int lr = lane >> 2, lc = lane & 3;
    const int* cb = cols + k16 * 16;
    int c0 = __ldg(cb + 2 * lc);
    int c1 = __ldg(cb + 2 * lc + 1);
    int c2 = __ldg(cb + 2 * lc + 8);
    int c3 = __ldg(cb + 2 * lc + 9);
    const float* r1 = x + (size_t)(m_atom * 16 + lr) * FIN;
    const float* r2 = r1 + (size_t)8 * FIN;
    uint4 o;
    o.x = pack_h2(__ldg(r1 + c0), __ldg(r1 + c1));
    o.y = pack_h2(__ldg(r2 + c0), __ldg(r2 + c1));
    o.z = pack_h2(__ldg(r1 + c2), __ldg(r1 + c3));
    o.w = pack_h2(__ldg(r2 + c2), __ldg(r2 + c3));
    g_xc[t] = o;
}

// Kernel 1b: weights -> alpha-folded fp16, pair-packed B-fragment layout.
__global__ void wconv_kernel(const float* __restrict__ w) {
    int t = blockIdx.x * blockDim.x + threadIdx.x;
    int lane = t & 31;
    int k16  = (t >> 5) & (K16S - 1);
    int np   = t >> 12;
    int lr = lane >> 2, lc2 = 2 * (lane & 3);
    const float* wlo = w + (size_t)(np * 16 + lr) * KC + k16 * 16 + lc2;
    const float* whi = wlo + (size_t)8 * KC;
    uint4 o;
    o.x = pack_h2(__ldg(wlo)     * ALPHA_S, __ldg(wlo + 1) * ALPHA_S);
    o.y = pack_h2(__ldg(wlo + 8) * ALPHA_S, __ldg(wlo + 9) * ALPHA_S);
    o.z = pack_h2(__ldg(whi)     * ALPHA_S, __ldg(whi + 1) * ALPHA_S);
    o.w = pack_h2(__ldg(whi + 8) * ALPHA_S, __ldg(whi + 9) * ALPHA_S);
    g_wt4[t] = o;
}

// Kernel 1c: build sorted inactive-channel list (1 block, deterministic).
__global__ void inactive_kernel(const int* __restrict__ rows) {
    __shared__ char act[FOUT];
    __shared__ int  base[128];
    const int tid = threadIdx.x;
    for (int i = tid; i < FOUT; i += blockDim.x) act[i] = 0;
    __syncthreads();
    for (int i = tid; i < NR; i += blockDim.x) act[__ldg(&rows[i])] = 1;
    __syncthreads();
    if (tid < 128) {
        int c = 0;
        #pragma unroll
        for (int j = 0; j < 32; ++j) c += !act[tid * 32 + j];
        base[tid] = c;
    }
    __syncthreads();
    if (tid == 0) {
        int s = 0;
        for (int i = 0; i < 128; ++i) { int c = base[i]; base[i] = s; s += c; }
    }
    __syncthreads();
    if (tid < 128) {
        int o = base[tid];
        #pragma unroll
        for (int j = 0; j < 32; ++j) {
            int ch = tid * 32 + j;
            if (!act[ch]) g_inact[o++] = ch;
        }
    }
}

// ---------------------------------------------------------------------------
// Kernel 3: fp16 mma.sync GEMM. 4 warps (2m x 2n), warp tile 32x64,
// all-LDS128 fragment loads, 3-stage cp.async pipeline, 1 barrier/k-tile,
// 3 CTAs/SM (12 warps/SM) for latency hiding.
__global__ __launch_bounds__(THREADS, 3) void gemm_kernel(
    const float* __restrict__ bias,
    const int* __restrict__ rows,
    float* __restrict__ out)
{
    extern __shared__ char smem[];
    __shared__ int   sicols[128];
    __shared__ float sibias[128];
    const uint32_t sbase = smem_to_u32(smem);
    const int tid = threadIdx.x;
    const int wid = tid >> 5;
    const int lid = tid & 31;
    const int n0 = blockIdx.x * BN;
    const int m0 = blockIdx.y * BM;

    int*   srows = (int*)(smem + OFF_ROWS);
    float* sbias = (float*)(smem + OFF_BIAS);
    {
        int r = __ldg(&rows[n0 + tid]);
        srows[tid] = r;
        sbias[tid] = __ldg(&bias[r]);
        int ic = g_inact[n0 + tid];          // this x-tile's inactive slice
        sicols[tid] = ic;
        sibias[tid] = __ldg(&bias[ic]);
    }

    // stage fill: 1536 16B chunks (A:512 then B:1024), 12 per thread.
    auto refill = [&](int kt, int s) {
        const uint32_t stg = sbase + OFF_TILES + s * STAGE_BYTES;
        #pragma unroll
        for (int i = 0; i < 12; ++i) {
            int c = tid + i * THREADS;
            uint32_t dst = stg + c * 16;
            const void* src;
            if (c < 512) {                  // A: atom = m_atom_l*4 + k16_l
                int atom = c >> 5, lane = c & 31;
                int m_atom_g = (m0 >> 4) + (atom >> 2);
                int k16_g    = kt * 4 + (atom & 3);
                src = (const void*)(g_xc + ((size_t)m_atom_g * K16S + k16_g) * 32 + lane);
            } else {                        // B: cc = (p*4 + k16_l)*32 + lane
                int cc = c - 512;
                int p = cc >> 7, k16l = (cc >> 5) & 3, lane = cc & 31;
                int np_g  = (n0 >> 4) + p;
                int k16_g = kt * 4 + k16l;
                src = (const void*)(g_wt4 + ((size_t)np_g * K16S + k16_g) * 32 + lane);
            }
            CP_ASYNC16(dst, src);
        }
    };

    refill(0, 0); CP_COMMIT();
    refill(1, 1); CP_COMMIT();

    const int ma = (wid & 1) * 2;    // warp m-atom base (2 atoms = 32 rows)
    const int nb = (wid >> 1) * 8;   // warp n-atom base (8 atoms = 64 cols)
    const int pb = (wid >> 1) * 4;   // warp n-pair base (4 pairs)

    float acc[2][8][4];
    #pragma unroll
    for (int mt = 0; mt < 2; ++mt)
        #pragma unroll
        for (int nt = 0; nt < 8; ++nt)
            #pragma unroll
            for (int i = 0; i < 4; ++i) acc[mt][nt][i] = 0.f;

    for (int kt = 0; kt < KTILES; ++kt) {
        const int s = kt % STAGES;
        CP_WAIT1();
        // publishes stage s AND orders prior reads of the stage about to be
        // refilled -> single barrier per k-tile.
        __syncthreads();
        if (kt + 2 < KTILES) refill(kt + 2, (kt + 2) % STAGES);
        CP_COMMIT();

        const uint32_t stg = sbase + OFF_TILES + s * STAGE_BYTES;
        const uint32_t aW  = stg + lid * 16;            // + atom*512
        const uint32_t bW  = stg + A_BYTES + lid * 16;  // + (pair*4+k16)*512

        #pragma unroll
        for (int k16 = 0; k16 < 4; ++k16) {
            uint32_t a[2][4], b4[4][4];
            #pragma unroll
            for (int mt = 0; mt < 2; ++mt)
                LDS128(a[mt], aW + ((ma + mt) * 4 + k16) * 512);
            #pragma unroll
            for (int j = 0; j < 4; ++j)
                LDS128(b4[j], bW + ((pb + j) * 4 + k16) * 512);
            #pragma unroll
            for (int mt = 0; mt < 2; ++mt)
                #pragma unroll
                for (int nt = 0; nt < 8; ++nt)
                    mma_f16(acc[mt][nt], a[mt], &b4[nt >> 1][(nt & 1) * 2]);
        }
    }

    // epilogue A: scatter acc + bias to active output channels (alpha in W)
    const int lr = lid >> 2;
    const int lc = lid & 3;
    #pragma unroll
    for (int mt = 0; mt < 2; ++mt) {
        int mA = m0 + (ma + mt) * 16 + lr;
        float* rowA = out + (size_t)mA * FOUT;
        float* rowB = rowA + (size_t)8 * FOUT;
        #pragma unroll
        for (int nt = 0; nt < 8; ++nt) {
            int nloc = (nb + nt) * 8 + lc * 2;
            int r0 = srows[nloc], r1 = srows[nloc + 1];
            float b0 = sbias[nloc], b1 = sbias[nloc + 1];
            rowA[r0] = acc[mt][nt][0] + b0;
            rowA[r1] = acc[mt][nt][1] + b1;
            rowB[r0] = acc[mt][nt][2] + b0;
            rowB[r1] = acc[mt][nt][3] + b1;
        }
    }

    // epilogue B: bias to this CTA's slice of inactive channels.
    // 64 rows x 128 inactive cols = 8192 elems, 64 per thread.
    #pragma unroll
    for (int i = 0; i < 64; ++i) {
        int idx = tid + i * THREADS;         // 0..8191
        int row = idx >> 7, col = idx & 127;
        out[(size_t)(m0 + row) * FOUT + sicols[col]] = sibias[col];
    }
}

// ---------------------------------------------------------------------------
extern "C" void kernel_launch(void* const* d_in, const int* in_sizes, int n_in,
                              void* d_out, int out_size) {
    const float* x    = (const float*)d_in[0];
    const float* w    = (const float*)d_in[1];
    const float* bias = (const float*)d_in[2];
    const int*   rows = (const int*)d_in[3];
    const int*   cols = (const int*)d_in[4];
    float*       out  = (float*)d_out;

    cudaFuncSetAttribute(gemm_kernel, cudaFuncAttributeMaxDynamicSharedMemorySize,
                         SMEM_TOTAL);

    gather_kernel<<<(MT / 16) * K16S * 32 / 256, 256>>>(x, cols);
    wconv_kernel<<<(NR / 16) * K16S * 32 / 256, 256>>>(w);
    inactive_kernel<<<1, 1024>>>(rows);
    gemm_kernel<<<dim3(NR / BN, MT / BM), THREADS, SMEM_TOTAL>>>(bias, rows, out);
}

// round 17
// speedup vs baseline: 1.1494x; 1.0147x over previous
#include <cuda_runtime.h>
#include <cuda_fp16.h>
#include <cstdint>

// SparseChannelLinear: gather(cols)+fp16 -> fp16 mma.sync m16n8k16 GEMM
// (fragment-packed A, pair-packed B, BM=64, 2-stage pipeline, 3 CTAs/SM)
// -> fused epilogue: active cols = acc+bias, inactive cols = bias.

#define ALPHA_S 0.05f

static constexpr int MT   = 8192;
static constexpr int KC   = 2048;
static constexpr int NR   = 2048;
static constexpr int FIN  = 4096;
static constexpr int FOUT = 4096;
static constexpr int NINACT = FOUT - NR;            // 2048

static constexpr int BM = 64, BN = 128, BK = 64;    // BK elements (4 k16-atoms)
static constexpr int STAGES  = 2;
static constexpr int KTILES  = KC / BK;             // 32
static constexpr int THREADS = 128;                 // 4 warps, 2m x 2n of 32x64

static constexpr int K16S = KC / 16;                // 128 k16-atoms total

// dynamic smem: header (rows/bias/icols/ibias), then 2 stages of (A 8K + B 16K)
static constexpr int OFF_ROWS    = 0;      // 128 x int
static constexpr int OFF_BIAS    = 512;    // 128 x float
static constexpr int OFF_ICOL    = 1024;   // 128 x int
static constexpr int OFF_IBIA    = 1536;   // 128 x float
static constexpr int OFF_TILES   = 2048;
static constexpr int A_BYTES     = BM * BK * 2;           // 8192
static constexpr int B_BYTES     = BN * BK * 2;           // 16384
static constexpr int STAGE_BYTES = A_BYTES + B_BYTES;     // 24576
static constexpr int SMEM_TOTAL  = OFF_TILES + STAGES * STAGE_BYTES;  // 51200

// scratch:
// g_xc: A fragments. [m_atom(512)][k16(128)][lane(32)] x uint4 (regs a0..a3)
// g_wt4: B fragments pair-packed (alpha-folded). [n_pair(128)][k16(128)][lane(32)]
__device__ uint4 g_xc [(size_t)(MT / 16) * K16S * 32];
__device__ uint4 g_wt4[(size_t)(NR / 16) * K16S * 32];
__device__ int   g_inact[NINACT];   // sorted list of inactive output channels

// ---------------------------------------------------------------------------
__device__ __forceinline__ uint32_t smem_to_u32(const void* p) {
    uint32_t a;
    asm("{ .reg .u64 t; cvta.to.shared.u64 t, %1; cvt.u32.u64 %0, t; }" : "=r"(a) : "l"(p));
    return a;
}
__device__ __forceinline__ uint32_t pack_h2(float lo, float hi) {
    __half2 h = __floats2half2_rn(lo, hi);
    return *reinterpret_cast<uint32_t*>(&h);
}
#define CP_ASYNC16(dst, src) \
    asm volatile("cp.async.cg.shared.global [%0], [%1], 16;" :: "r"(dst), "l"(src))
#define CP_COMMIT() asm volatile("cp.async.commit_group;" ::: "memory")
#define CP_WAIT0()  asm volatile("cp.async.wait_group 0;" ::: "memory")

#define LDS128(r, addr) \
    asm volatile("ld.shared.v4.b32 {%0,%1,%2,%3}, [%4];" \
        : "=r"((r)[0]), "=r"((r)[1]), "=r"((r)[2]), "=r"((r)[3]) : "r"(addr))

__device__ __forceinline__ void mma_f16(float* c, const uint32_t* a, const uint32_t* b) {
    asm volatile(
        "mma.sync.aligned.m16n8k16.row.col.f32.f16.f16.f32 "
        "{%0,%1,%2,%3}, {%4,%5,%6,%7}, {%8,%9}, {%0,%1,%2,%3};"
        : "+f"(c[0]), "+f"(c[1]), "+f"(c[2]), "+f"(c[3])
        : "r"(a[0]), "r"(a[1]), "r"(a[2]), "r"(a[3]), "r"(b[0]), "r"(b[1]));
}

// ---------------------------------------------------------------------------
// Kernel 1: gather active input channels into fp16 A-fragment-packed layout.
__global__ void gather_kernel(const float* __restrict__ x,
                              const int* __restrict__ cols) {
    int t = blockIdx.x * blockDim.x + threadIdx.x;
    int lane   = t & 31;
    int k16    = (t >> 5) & (K16S - 1);
    int m_atom = t >> 12;
    int lr = lane >> 2, lc = lane & 3;
    const int* cb = cols + k16 * 16;
    int c0 = __ldg(cb + 2 * lc);
    int c1 = __ldg(cb + 2 * lc + 1);
    int c2 = __ldg(cb + 2 * lc + 8);
    int c3 = __ldg(cb + 2 * lc + 9);
    const float* r1 = x + (size_t)(m_atom * 16 + lr) * FIN;
    const float* r2 = r1 + (size_t)8 * FIN;
    uint4 o;
    o.x = pack_h2(__ldg(r1 + c0), __ldg(r1 + c1));
    o.y = pack_h2(__ldg(r2 + c0), __ldg(r2 + c1));
    o.z = pack_h2(__ldg(r1 + c2), __ldg(r1 + c3));
    o.w = pack_h2(__ldg(r2 + c2), __ldg(r2 + c3));
    g_xc[t] = o;
}

// Kernel 1b: weights -> alpha-folded fp16, pair-packed B-fragment layout.
__global__ void wconv_kernel(const float* __restrict__ w) {
    int t = blockIdx.x * blockDim.x + threadIdx.x;
    int lane = t & 31;
    int k16  = (t >> 5) & (K16S - 1);
    int np   = t >> 12;
    int lr = lane >> 2, lc2 = 2 * (lane & 3);
    const float* wlo = w + (size_t)(np * 16 + lr) * KC + k16 * 16 + lc2;
    const float* whi = wlo + (size_t)8 * KC;
    uint4 o;
    o.x = pack_h2(__ldg(wlo)     * ALPHA_S, __ldg(wlo + 1) * ALPHA_S);
    o.y = pack_h2(__ldg(wlo + 8) * ALPHA_S, __ldg(wlo + 9) * ALPHA_S);
    o.z = pack_h2(__ldg(whi)     * ALPHA_S, __ldg(whi + 1) * ALPHA_S);
    o.w = pack_h2(__ldg(whi + 8) * ALPHA_S, __ldg(whi + 9) * ALPHA_S);
    g_wt4[t] = o;
}

// Kernel 1c: build sorted inactive-channel list (1 block, deterministic).
__global__ void inactive_kernel(const int* __restrict__ rows) {
    __shared__ char act[FOUT];
    __shared__ int  base[128];
    const int tid = threadIdx.x;
    for (int i = tid; i < FOUT; i += blockDim.x) act[i] = 0;
    __syncthreads();
    for (int i = tid; i < NR; i += blockDim.x) act[__ldg(&rows[i])] = 1;
    __syncthreads();
    if (tid < 128) {
        int c = 0;
        #pragma unroll
        for (int j = 0; j < 32; ++j) c += !act[tid * 32 + j];
        base[tid] = c;
    }
    __syncthreads();
    if (tid == 0) {
        int s = 0;
        for (int i = 0; i < 128; ++i) { int c = base[i]; base[i] = s; s += c; }
    }
    __syncthreads();
    if (tid < 128) {
        int o = base[tid];
        #pragma unroll
        for (int j = 0; j < 32; ++j) {
            int ch = tid * 32 + j;
            if (!act[ch]) g_inact[o++] = ch;
        }
    }
}

// ---------------------------------------------------------------------------
// Kernel 3: fp16 mma.sync GEMM. 4 warps (2m x 2n), warp tile 32x64,
// all-LDS128 fragment loads, 2-stage cp.async double buffer (wait_group 0;
// next tile's copy issued before current tile's compute -> full overlap),
// 3 CTAs/SM (12 warps/SM).
__global__ __launch_bounds__(THREADS, 3) void gemm_kernel(
    const float* __restrict__ bias,
    const int* __restrict__ rows,
    float* __restrict__ out)
{
    extern __shared__ char smem[];
    const uint32_t sbase = smem_to_u32(smem);
    const int tid = threadIdx.x;
    const int wid = tid >> 5;
    const int lid = tid & 31;
    const int n0 = blockIdx.x * BN;
    const int m0 = blockIdx.y * BM;

    int*   srows  = (int*)(smem + OFF_ROWS);
    float* sbias  = (float*)(smem + OFF_BIAS);
    int*   sicols = (int*)(smem + OFF_ICOL);
    float* sibias = (float*)(smem + OFF_IBIA);
    {
        int r = __ldg(&rows[n0 + tid]);
        srows[tid] = r;
        sbias[tid] = __ldg(&bias[r]);
        int ic = g_inact[n0 + tid];          // this x-tile's inactive slice
        sicols[tid] = ic;
        sibias[tid] = __ldg(&bias[ic]);
    }

    // stage fill: 1536 16B chunks (A:512 then B:1024), 12 per thread.
    auto refill = [&](int kt, int s) {
        const uint32_t stg = sbase + OFF_TILES + s * STAGE_BYTES;
        #pragma unroll
        for (int i = 0; i < 12; ++i) {
            int c = tid + i * THREADS;
            uint32_t dst = stg + c * 16;
            const void* src;
            if (c < 512) {                  // A: atom = m_atom_l*4 + k16_l
                int atom = c >> 5, lane = c & 31;
                int m_atom_g = (m0 >> 4) + (atom >> 2);
                int k16_g    = kt * 4 + (atom & 3);
                src = (const void*)(g_xc + ((size_t)m_atom_g * K16S + k16_g) * 32 + lane);
            } else {                        // B: cc = (p*4 + k16_l)*32 + lane
                int cc = c - 512;
                int p = cc >> 7, k16l = (cc >> 5) & 3, lane = cc & 31;
                int np_g  = (n0 >> 4) + p;
                int k16_g = kt * 4 + k16l;
                src = (const void*)(g_wt4 + ((size_t)np_g * K16S + k16_g) * 32 + lane);
            }
            CP_ASYNC16(dst, src);
        }
    };

    refill(0, 0); CP_COMMIT();

    const int ma = (wid & 1) * 2;    // warp m-atom base (2 atoms = 32 rows)
    const int nb = (wid >> 1) * 8;   // warp n-atom base (8 atoms = 64 cols)
    const int pb = (wid >> 1) * 4;   // warp n-pair base (4 pairs)

    float acc[2][8][4];
    #pragma unroll
    for (int mt = 0; mt < 2; ++mt)
        #pragma unroll
        for (int nt = 0; nt < 8; ++nt)
            #pragma unroll
            for (int i = 0; i < 4; ++i) acc[mt][nt][i] = 0.f;

    for (int kt = 0; kt < KTILES; ++kt) {
        const int s = kt & 1;
        CP_WAIT0();                  // stage kt complete (sole outstanding group)
        // barrier publishes stage s and orders last iteration's reads of
        // stage s^1 before the refill below overwrites it.
        __syncthreads();
        if (kt + 1 < KTILES) refill(kt + 1, s ^ 1);
        CP_COMMIT();

        const uint32_t stg = sbase + OFF_TILES + s * STAGE_BYTES;
        const uint32_t aW  = stg + lid * 16;            // + atom*512
        const uint32_t bW  = stg + A_BYTES + lid * 16;  // + (pair*4+k16)*512

        #pragma unroll
        for (int k16 = 0; k16 < 4; ++k16) {
            uint32_t a[2][4], b4[4][4];
            #pragma unroll
            for (int mt = 0; mt < 2; ++mt)
                LDS128(a[mt], aW + ((ma + mt) * 4 + k16) * 512);
            #pragma unroll
            for (int j = 0; j < 4; ++j)
                LDS128(b4[j], bW + ((pb + j) * 4 + k16) * 512);
            #pragma unroll
            for (int mt = 0; mt < 2; ++mt)
                #pragma unroll
                for (int nt = 0; nt < 8; ++nt)
                    mma_f16(acc[mt][nt], a[mt], &b4[nt >> 1][(nt & 1) * 2]);
        }
    }

    // epilogue A: scatter acc + bias to active output channels (alpha in W)
    const int lr = lid >> 2;
    const int lc = lid & 3;
    #pragma unroll
    for (int mt = 0; mt < 2; ++mt) {
        int mA = m0 + (ma + mt) * 16 + lr;
        float* rowA = out + (size_t)mA * FOUT;
        float* rowB = rowA + (size_t)8 * FOUT;
        #pragma unroll
        for (int nt = 0; nt < 8; ++nt) {
            int nloc = (nb + nt) * 8 + lc * 2;
            int r0 = srows[nloc], r1 = srows[nloc + 1];
            float b0 = sbias[nloc], b1 = sbias[nloc + 1];
            rowA[r0] = acc[mt][nt][0] + b0;
            rowA[r1] = acc[mt][nt][1] + b1;
            rowB[r0] = acc[mt][nt][2] + b0;
            rowB[r1] = acc[mt][nt][3] + b1;
        }
    }

    // epilogue B: bias to this CTA's slice of inactive channels.
    // 64 rows x 128 inactive cols = 8192 elems, 64 per thread.
    #pragma unroll
    for (int i = 0; i < 64; ++i) {
        int idx = tid + i * THREADS;         // 0..8191
        int row = idx >> 7, col = idx & 127;
        out[(size_t)(m0 + row) * FOUT + sicols[col]] = sibias[col];
    }
}

// ---------------------------------------------------------------------------
extern "C" void kernel_launch(void* const* d_in, const int* in_sizes, int n_in,
                              void* d_out, int out_size) {
    const float* x    = (const float*)d_in[0];
    const float* w    = (const float*)d_in[1];
    const float* bias = (const float*)d_in[2];
    const int*   rows = (const int*)d_in[3];
    const int*   cols = (const int*)d_in[4];
    float*       out  = (float*)d_out;

    cudaFuncSetAttribute(gemm_kernel, cudaFuncAttributeMaxDynamicSharedMemorySize,
                         SMEM_TOTAL);

    gather_kernel<<<(MT / 16) * K16S * 32 / 256, 256>>>(x, cols);
    wconv_kernel<<<(NR / 16) * K16S * 32 / 256, 256>>>(w);
    inactive_kernel<<<1, 1024>>>(rows);
    gemm_kernel<<<dim3(NR / BN, MT / BM), THREADS, SMEM_TOTAL>>>(bias, rows, out);
}